// round 14
// baseline (speedup 1.0000x reference)
#include <cuda_runtime.h>
#include <cuda_bf16.h>
#include <cstdint>
#include <math.h>

#define BATCH 8192
#define IN_F  2048
#define OUT_F 2048
#define LN2F  0.69314718055994531f
#define PHI_ONE 0.62011450695827750f   // softplus(1) - ln2

#define BM 128
#define BN 128
#define BK 32
#define NCH (IN_F / BK)          // 64 chunks
#define PAD_H 40                 // smem halves per row (32 data + 8 pad)
#define ROWB (PAD_H * 2)         // 80 bytes per row
#define MTILE_B (BM * ROWB)      // 10240 B per operand tile
#define BUF_B (4 * MTILE_B)      // Ah, Al, Bh, Bl
#define DSMEM_BYTES (2 * BUF_B)  // 81920 B double-buffered

// ---- device scratch (allocation-free rule); 16B-aligned ----
__device__ __align__(16) __nv_bfloat16 g_Ah[(size_t)BATCH * IN_F];
__device__ __align__(16) __nv_bfloat16 g_Al[(size_t)BATCH * IN_F];
__device__ __align__(16) __nv_bfloat16 g_Bh[(size_t)OUT_F * IN_F];
__device__ __align__(16) __nv_bfloat16 g_Bl[(size_t)OUT_F * IN_F];
__device__ float g_biasc[OUT_F];

// ---------------- helpers ----------------
__device__ __forceinline__ uint32_t smem_u32(const void* p) {
    uint32_t a;
    asm("{ .reg .u64 t; cvta.to.shared.u64 t, %1; cvt.u32.u64 %0, t; }"
        : "=r"(a) : "l"(p));
    return a;
}
__device__ __forceinline__ void ldsm_x4(uint32_t* r, uint32_t addr) {
    asm volatile("ldmatrix.sync.aligned.m8n8.x4.shared.b16 {%0,%1,%2,%3}, [%4];"
                 : "=r"(r[0]), "=r"(r[1]), "=r"(r[2]), "=r"(r[3]) : "r"(addr));
}
__device__ __forceinline__ void cp16(uint32_t dst, const void* src) {
    asm volatile("cp.async.cg.shared.global [%0], [%1], 16;"
                 :: "r"(dst), "l"(src) : "memory");
}
#define CP_COMMIT() asm volatile("cp.async.commit_group;" ::: "memory")
#define CP_WAIT(n)  asm volatile("cp.async.wait_group %0;" :: "n"(n) : "memory")

__device__ __forceinline__ void mma_bf16(float* c, const uint32_t* a,
                                         uint32_t b0, uint32_t b1) {
    asm volatile(
        "mma.sync.aligned.m16n8k16.row.col.f32.bf16.bf16.f32 "
        "{%0,%1,%2,%3}, {%4,%5,%6,%7}, {%8,%9}, {%0,%1,%2,%3};"
        : "+f"(c[0]), "+f"(c[1]), "+f"(c[2]), "+f"(c[3])
        : "r"(a[0]), "r"(a[1]), "r"(a[2]), "r"(a[3]), "r"(b0), "r"(b1));
}

// ---------------------------------------------------------------------------
// phi = softplus(x) - ln2, split to bf16 hi/lo
// ---------------------------------------------------------------------------
__device__ __forceinline__ float softplus_m_ln2(float x) {
    return fmaxf(x, 0.0f) + log1pf(__expf(-fabsf(x))) - LN2F;
}

__global__ void phi_split_kernel(const float* __restrict__ x) {
    int i = blockIdx.x * blockDim.x + threadIdx.x;   // float4 index
    float4 v = ((const float4*)x)[i];
    float p[4] = { softplus_m_ln2(v.x), softplus_m_ln2(v.y),
                   softplus_m_ln2(v.z), softplus_m_ln2(v.w) };
    uint32_t hh[2], ll[2];
    #pragma unroll
    for (int q = 0; q < 2; q++) {
        __nv_bfloat16 h0 = __float2bfloat16(p[2*q+0]);
        __nv_bfloat16 h1 = __float2bfloat16(p[2*q+1]);
        __nv_bfloat16 l0 = __float2bfloat16(p[2*q+0] - __bfloat162float(h0));
        __nv_bfloat16 l1 = __float2bfloat16(p[2*q+1] - __bfloat162float(h1));
        hh[q] = (uint32_t)__bfloat16_as_ushort(h0) |
                ((uint32_t)__bfloat16_as_ushort(h1) << 16);
        ll[q] = (uint32_t)__bfloat16_as_ushort(l0) |
                ((uint32_t)__bfloat16_as_ushort(l1) << 16);
    }
    ((uint2*)g_Ah)[i] = make_uint2(hh[0], hh[1]);
    ((uint2*)g_Al)[i] = make_uint2(ll[0], ll[1]);
}

__global__ void w_split_kernel(const float* __restrict__ W) {
    int idx = blockIdx.x * blockDim.x + threadIdx.x;   // o*K + k
    int o = idx >> 11;
    int k = idx & 2047;
    float v = W[(size_t)o * (IN_F + 1) + k];
    __nv_bfloat16 h = __float2bfloat16(v);
    g_Bh[idx] = h;
    g_Bl[idx] = __float2bfloat16(v - __bfloat162float(h));
}

__global__ void bias_kernel(const float* __restrict__ W) {
    int o = blockIdx.x * blockDim.x + threadIdx.x;
    g_biasc[o] = W[(size_t)o * (IN_F + 1) + IN_F] * PHI_ONE;
}

// ---------------------------------------------------------------------------
// HMMA GEMM: C = sum_K (AhBh + AlBh + AhBl) + bias  (fp32 accum)
// ldmatrix.x4 fragment loads; single __syncthreads per chunk.
// ---------------------------------------------------------------------------
__global__ void __launch_bounds__(256, 2) kan_mma(float* __restrict__ C) {
    extern __shared__ __align__(16) char dsm[];
    __shared__ float bias_sh[BN];

    const int tid = threadIdx.x;
    const int wid = tid >> 5, lane = tid & 31;
    const int bn = blockIdx.x * BN;
    const int bm = blockIdx.y * BM;
    const int wm = (wid & 1) * 64;   // warp m origin (2 m-warps)
    const int wn = (wid >> 1) * 32;  // warp n origin (4 n-warps)

    const uint32_t sbase = smem_u32(dsm);
    if (tid < BN) bias_sh[tid] = g_biasc[bn + tid];

    // ldmatrix lane offset: group = lane/8 picks (row+8?, +16B?); row = lane%8
    const int grp = lane >> 3, grow = lane & 7;
    const uint32_t frag_off = ((grp & 1) * 8 + grow) * ROWB + (grp >> 1) * 16;

    // global load mapping: idx = tid + 256*i -> row = idx/4, seg = idx%4 (16B)
    auto load_chunk = [&](int c, int buf) {
        uint32_t sb = sbase + buf * BUF_B;
        #pragma unroll
        for (int i = 0; i < 2; i++) {
            int idx = tid + 256 * i;
            int row = idx >> 2, seg = idx & 3;
            uint32_t d = sb + row * ROWB + seg * 16;
            size_t offA = (size_t)(bm + row) * IN_F + c * BK + seg * 8;
            size_t offB = (size_t)(bn + row) * IN_F + c * BK + seg * 8;
            cp16(d + 0 * MTILE_B, g_Ah + offA);
            cp16(d + 1 * MTILE_B, g_Al + offA);
            cp16(d + 2 * MTILE_B, g_Bh + offB);
            cp16(d + 3 * MTILE_B, g_Bl + offB);
        }
    };

    float acc[4][4][4];
    #pragma unroll
    for (int mi = 0; mi < 4; mi++)
        #pragma unroll
        for (int ni = 0; ni < 4; ni++)
            #pragma unroll
            for (int r = 0; r < 4; r++) acc[mi][ni][r] = 0.0f;

    load_chunk(0, 0);
    CP_COMMIT();

    for (int c = 0; c < NCH; c++) {
        const int buf = c & 1;
        // The only outstanding cp.async group here is chunk c's.
        CP_WAIT(0);
        // Barrier: (a) chunk c data visible CTA-wide, (b) all warps have
        // finished reading chunk c-1 (compute precedes this barrier in
        // program order), so writing chunk c+1 into buf^1 cannot race.
        __syncthreads();
        if (c + 1 < NCH) { load_chunk(c + 1, buf ^ 1); CP_COMMIT(); }

        const uint32_t sAh = sbase + buf * BUF_B;
        const uint32_t sAl = sAh + MTILE_B;
        const uint32_t sBh = sAl + MTILE_B;
        const uint32_t sBl = sBh + MTILE_B;

        #pragma unroll
        for (int ks = 0; ks < 2; ks++) {
            const uint32_t kb = ks * 32;   // k16 byte offset within row

            uint32_t ah[4][4];
            #pragma unroll
            for (int mi = 0; mi < 4; mi++)
                ldsm_x4(ah[mi], sAh + (wm + mi * 16) * ROWB + kb + frag_off);

            // B: one x4 covers two ni (16 n-rows x k16):
            //   regs {r0,r2} -> b(ni=2np), {r1,r3} -> b(ni=2np+1)
            uint32_t bh[2][4];
            #pragma unroll
            for (int np = 0; np < 2; np++)
                ldsm_x4(bh[np], sBh + (wn + np * 16) * ROWB + kb + frag_off);

            #pragma unroll
            for (int mi = 0; mi < 4; mi++)
                #pragma unroll
                for (int np = 0; np < 2; np++) {
                    mma_bf16(acc[mi][2*np+0], ah[mi], bh[np][0], bh[np][2]);
                    mma_bf16(acc[mi][2*np+1], ah[mi], bh[np][1], bh[np][3]);
                }

            {   // Al*Bh (load al after AhBh to cap register pressure)
                uint32_t al[4][4];
                #pragma unroll
                for (int mi = 0; mi < 4; mi++)
                    ldsm_x4(al[mi], sAl + (wm + mi * 16) * ROWB + kb + frag_off);
                #pragma unroll
                for (int mi = 0; mi < 4; mi++)
                    #pragma unroll
                    for (int np = 0; np < 2; np++) {
                        mma_bf16(acc[mi][2*np+0], al[mi], bh[np][0], bh[np][2]);
                        mma_bf16(acc[mi][2*np+1], al[mi], bh[np][1], bh[np][3]);
                    }
            }
            {   // Ah*Bl
                uint32_t bl[2][4];
                #pragma unroll
                for (int np = 0; np < 2; np++)
                    ldsm_x4(bl[np], sBl + (wn + np * 16) * ROWB + kb + frag_off);
                #pragma unroll
                for (int mi = 0; mi < 4; mi++)
                    #pragma unroll
                    for (int np = 0; np < 2; np++) {
                        mma_bf16(acc[mi][2*np+0], ah[mi], bl[np][0], bl[np][2]);
                        mma_bf16(acc[mi][2*np+1], ah[mi], bl[np][1], bl[np][3]);
                    }
            }
        }
    }

    // Epilogue: c0,c1 = row lane/4, cols 2*(lane&3)+{0,1}; c2,c3 = row+8
    const int lrow = lane >> 2;
    #pragma unroll
    for (int mi = 0; mi < 4; mi++) {
        int r0 = bm + wm + mi * 16 + lrow;
        #pragma unroll
        for (int ni = 0; ni < 4; ni++) {
            int cb = wn + ni * 8 + (lane & 3) * 2;      // within CTA tile
            float b0 = bias_sh[cb], b1 = bias_sh[cb + 1];
            float2 v0 = make_float2(acc[mi][ni][0] + b0, acc[mi][ni][1] + b1);
            float2 v1 = make_float2(acc[mi][ni][2] + b0, acc[mi][ni][3] + b1);
            *(float2*)&C[(size_t)r0 * OUT_F + bn + cb] = v0;
            *(float2*)&C[(size_t)(r0 + 8) * OUT_F + bn + cb] = v1;
        }
    }
}

// ---------------------------------------------------------------------------
extern "C" void kernel_launch(void* const* d_in, const int* in_sizes, int n_in,
                              void* d_out, int out_size) {
    // Identify inputs by element count (W is uniquely OUT_F*(IN_F+1)).
    const float* x = (const float*)d_in[0];
    const float* W = (const float*)d_in[1];
    if (n_in >= 2 && in_sizes[0] == OUT_F * (IN_F + 1)) {
        W = (const float*)d_in[0];
        x = (const float*)d_in[1];
    }
    float* out = (float*)d_out;               // (8192, 2048) fp32

    cudaFuncSetAttribute(kan_mma, cudaFuncAttributeMaxDynamicSharedMemorySize,
                         DSMEM_BYTES);

    phi_split_kernel<<<(BATCH * IN_F / 4) / 256, 256>>>(x);
    w_split_kernel<<<(OUT_F * IN_F) / 256, 256>>>(W);
    bias_kernel<<<OUT_F / 256, 256>>>(W);

    dim3 grid(OUT_F / BN, BATCH / BM);   // (16, 64)
    kan_mma<<<grid, 256, DSMEM_BYTES>>>(out);
}

// round 17
// speedup vs baseline: 1.5077x; 1.5077x over previous
#include <cuda_runtime.h>
#include <cstdint>
#include <math.h>

#define BATCH 8192
#define IN_F  2048
#define OUT_F 2048
#define LN2F  0.69314718055994531f
#define PHI_ONE 0.62011450695827750f   // softplus(1) - ln2

#define BM 128
#define BN 128
#define BK 32                    // fp32 elements per chunk (4 x k8 MMA steps)
#define NCH (IN_F / BK)          // 64 chunks
#define ROWW 36                  // smem words per row (32 data + 4 pad)
#define ROWB (ROWW * 4)          // 144 bytes per row
#define MTILE_B (BM * ROWB)      // 18432 B per operand tile
#define BUF_B (2 * MTILE_B)      // A, B tiles
#define DSMEM_BYTES (2 * BUF_B)  // 73728 B double-buffered

// ---- device scratch (allocation-free rule); 16B-aligned ----
__device__ __align__(16) float g_phi[(size_t)BATCH * IN_F];   // tf32-rounded
__device__ __align__(16) float g_Wp[(size_t)OUT_F * IN_F];    // tf32-rounded, repacked
__device__ float g_biasc[OUT_F];

// ---------------- helpers ----------------
__device__ __forceinline__ uint32_t smem_u32(const void* p) {
    uint32_t a;
    asm("{ .reg .u64 t; cvta.to.shared.u64 t, %1; cvt.u32.u64 %0, t; }"
        : "=r"(a) : "l"(p));
    return a;
}
__device__ __forceinline__ uint32_t lds32(uint32_t a) {
    uint32_t v;
    asm volatile("ld.shared.b32 %0, [%1];" : "=r"(v) : "r"(a));
    return v;
}
__device__ __forceinline__ void cp16(uint32_t dst, const void* src) {
    asm volatile("cp.async.cg.shared.global [%0], [%1], 16;"
                 :: "r"(dst), "l"(src) : "memory");
}
#define CP_COMMIT() asm volatile("cp.async.commit_group;" ::: "memory")
#define CP_WAIT(n)  asm volatile("cp.async.wait_group %0;" :: "n"(n) : "memory")

__device__ __forceinline__ float tf32_rna(float f) {
    uint32_t u;
    asm("cvt.rna.tf32.f32 %0, %1;" : "=r"(u) : "f"(f));
    return __uint_as_float(u);
}

__device__ __forceinline__ void mma_tf32(float* c, const uint32_t* a,
                                         uint32_t b0, uint32_t b1) {
    asm volatile(
        "mma.sync.aligned.m16n8k8.row.col.f32.tf32.tf32.f32 "
        "{%0,%1,%2,%3}, {%4,%5,%6,%7}, {%8,%9}, {%0,%1,%2,%3};"
        : "+f"(c[0]), "+f"(c[1]), "+f"(c[2]), "+f"(c[3])
        : "r"(a[0]), "r"(a[1]), "r"(a[2]), "r"(a[3]), "r"(b0), "r"(b1));
}

// ---------------------------------------------------------------------------
// phi = softplus(x) - ln2, tf32-rounded
// ---------------------------------------------------------------------------
__device__ __forceinline__ float softplus_m_ln2(float x) {
    return fmaxf(x, 0.0f) + log1pf(__expf(-fabsf(x))) - LN2F;
}

__global__ void phi_kernel(const float* __restrict__ x) {
    int i = blockIdx.x * blockDim.x + threadIdx.x;   // float4 index
    float4 v = ((const float4*)x)[i];
    float4 r;
    r.x = tf32_rna(softplus_m_ln2(v.x));
    r.y = tf32_rna(softplus_m_ln2(v.y));
    r.z = tf32_rna(softplus_m_ln2(v.z));
    r.w = tf32_rna(softplus_m_ln2(v.w));
    ((float4*)g_phi)[i] = r;
}

// W(O, K+1) -> tf32-rounded first K columns, stride-2048 repack
__global__ void w_pack_kernel(const float* __restrict__ W) {
    int idx = blockIdx.x * blockDim.x + threadIdx.x;   // o*K + k
    int o = idx >> 11;
    int k = idx & 2047;
    g_Wp[idx] = tf32_rna(W[(size_t)o * (IN_F + 1) + k]);
}

__global__ void bias_kernel(const float* __restrict__ W) {
    int o = blockIdx.x * blockDim.x + threadIdx.x;
    g_biasc[o] = W[(size_t)o * (IN_F + 1) + IN_F] * PHI_ONE;
}

// ---------------------------------------------------------------------------
// tf32 HMMA GEMM: C = phi @ Wp^T + bias  (fp32 accum, single pass)
// Proven 2-sync / CP_WAIT(1) pipeline from the 588us kernel.
// ---------------------------------------------------------------------------
__global__ void __launch_bounds__(256, 2) kan_mma(float* __restrict__ C) {
    extern __shared__ __align__(16) char dsm[];
    __shared__ float bias_sh[BN];

    const int tid = threadIdx.x;
    const int wid = tid >> 5, lane = tid & 31;
    const int bn = blockIdx.x * BN;
    const int bm = blockIdx.y * BM;
    const int wm = (wid & 1) * 64;   // warp m origin (2 m-warps)
    const int wn = (wid >> 1) * 32;  // warp n origin (4 n-warps)

    const uint32_t sbase = smem_u32(dsm);
    if (tid < BN) bias_sh[tid] = g_biasc[bn + tid];

    // global load mapping: idx = tid + 256*i -> row = idx/8, seg = idx%8 (16B)
    auto load_chunk = [&](int c, int buf) {
        uint32_t sb = sbase + buf * BUF_B;
        #pragma unroll
        for (int i = 0; i < 4; i++) {
            int idx = tid + 256 * i;
            int row = idx >> 3, seg = idx & 7;
            uint32_t d = sb + row * ROWB + seg * 16;
            size_t offA = (size_t)(bm + row) * IN_F + c * BK + seg * 4;
            size_t offB = (size_t)(bn + row) * IN_F + c * BK + seg * 4;
            cp16(d, g_phi + offA);                 // A tile
            cp16(d + MTILE_B, g_Wp + offB);        // B tile
        }
    };

    float acc[4][4][4];
    #pragma unroll
    for (int mi = 0; mi < 4; mi++)
        #pragma unroll
        for (int ni = 0; ni < 4; ni++)
            #pragma unroll
            for (int r = 0; r < 4; r++) acc[mi][ni][r] = 0.0f;

    load_chunk(0, 0);
    CP_COMMIT();

    const int lrow = lane >> 2;            // 0..7 (m-row / n-row in fragment)
    const int lkb  = (lane & 3) * 4;       // k byte offset within k8 group

    for (int c = 0; c < NCH; c++) {
        const int buf = c & 1;
        if (c + 1 < NCH) { load_chunk(c + 1, buf ^ 1); CP_COMMIT(); CP_WAIT(1); }
        else             { CP_WAIT(0); }
        __syncthreads();

        const uint32_t sA = sbase + buf * BUF_B;
        const uint32_t sB = sA + MTILE_B;

        #pragma unroll
        for (int ks = 0; ks < 4; ks++) {
            const uint32_t kb = ks * 32 + lkb;   // byte offset within row

            // A fragment (m16k8 tf32): a0=(r,c) a1=(r+8,c) a2=(r,c+4) a3=(r+8,c+4)
            uint32_t a[4][4];
            #pragma unroll
            for (int mi = 0; mi < 4; mi++) {
                uint32_t b0 = sA + (wm + mi * 16 + lrow) * ROWB + kb;
                a[mi][0] = lds32(b0);
                a[mi][1] = lds32(b0 + 8 * ROWB);
                a[mi][2] = lds32(b0 + 16);
                a[mi][3] = lds32(b0 + 8 * ROWB + 16);
            }
            // B fragment (k8n8 tf32, col-major): b0=(c,n) b1=(c+4,n); n = lrow
            uint32_t b[4][2];
            #pragma unroll
            for (int ni = 0; ni < 4; ni++) {
                uint32_t base = sB + (wn + ni * 8 + lrow) * ROWB + kb;
                b[ni][0] = lds32(base);
                b[ni][1] = lds32(base + 16);
            }
            #pragma unroll
            for (int mi = 0; mi < 4; mi++)
                #pragma unroll
                for (int ni = 0; ni < 4; ni++)
                    mma_tf32(acc[mi][ni], a[mi], b[ni][0], b[ni][1]);
        }
        __syncthreads();
    }

    // Epilogue: c0,c1 = row lrow, cols 2*(lane&3)+{0,1}; c2,c3 = row+8
    #pragma unroll
    for (int mi = 0; mi < 4; mi++) {
        int r0 = bm + wm + mi * 16 + lrow;
        #pragma unroll
        for (int ni = 0; ni < 4; ni++) {
            int cb = wn + ni * 8 + (lane & 3) * 2;      // within CTA tile
            float b0 = bias_sh[cb], b1 = bias_sh[cb + 1];
            float2 v0 = make_float2(acc[mi][ni][0] + b0, acc[mi][ni][1] + b1);
            float2 v1 = make_float2(acc[mi][ni][2] + b0, acc[mi][ni][3] + b1);
            *(float2*)&C[(size_t)r0 * OUT_F + bn + cb] = v0;
            *(float2*)&C[(size_t)(r0 + 8) * OUT_F + bn + cb] = v1;
        }
    }
}

// ---------------------------------------------------------------------------
extern "C" void kernel_launch(void* const* d_in, const int* in_sizes, int n_in,
                              void* d_out, int out_size) {
    // Identify inputs by element count (W is uniquely OUT_F*(IN_F+1)).
    const float* x = (const float*)d_in[0];
    const float* W = (const float*)d_in[1];
    if (n_in >= 2 && in_sizes[0] == OUT_F * (IN_F + 1)) {
        W = (const float*)d_in[0];
        x = (const float*)d_in[1];
    }
    float* out = (float*)d_out;               // (8192, 2048) fp32

    cudaFuncSetAttribute(kan_mma, cudaFuncAttributeMaxDynamicSharedMemorySize,
                         DSMEM_BYTES);

    phi_kernel<<<(BATCH * IN_F / 4) / 256, 256>>>(x);
    w_pack_kernel<<<(OUT_F * IN_F) / 256, 256>>>(W);
    bias_kernel<<<OUT_F / 256, 256>>>(W);

    dim3 grid(OUT_F / BN, BATCH / BM);   // (16, 64)
    kan_mma<<<grid, 256, DSMEM_BYTES>>>(out);
}